// round 14
// baseline (speedup 1.0000x reference)
#include <cuda_runtime.h>
#include <cuda_bf16.h>
#include <math.h>
#include <stdint.h>

// Problem constants
#define NN 50000
#define NE 800000
#define DD 128
#define NC 2
#define SCAN_T 1024
#define SCAN_CH 49          // ceil(NN / SCAN_T)
#define AS 136              // smem row stride (bf16) for GEMM
#define GR 128              // rows per GEMM block
#define GT 256              // threads per GEMM block
#define ADJ_CAP (NE + 3 * NN)   // CSR padded to multiple of 4 per node

// ---------------- scratch (static device memory; no allocation) ----------------
__device__ int   g_cnt[NN];          // in-degree -- zeroed by edge2 tail
__device__ int   g_offs[NN + 1];     // CSR row offsets (padded to x4)
__device__ int   g_cursor[NN];       // scatter cursors
__device__ __align__(16) int2 g_adj[ADJ_CAP];  // (src byte-offset, coef bits)
__device__ float g_inv[NN];          // deg^{-1/2}
__device__ __align__(16) __nv_bfloat16 g_hb[NN * DD];  // GEMM output (bf16)
__device__ __align__(16) __nv_bfloat16 g_ab[NN * DD];  // post-ReLU activations
__device__ __align__(16) __nv_bfloat16 g_wb[DD * DD];  // W2 pre-converted bf16
__device__ float g_pool[DD];         // pool sums -- zeroed by finalize tail

// ---------------- PTX helpers ----------------
__device__ __forceinline__ uint32_t s2u(const void* p) {
    uint32_t a;
    asm("{ .reg .u64 t; cvta.to.shared.u64 t, %1; cvt.u32.u64 %0, t; }"
        : "=r"(a) : "l"(p));
    return a;
}
__device__ __forceinline__ void ldmA(uint32_t& a0, uint32_t& a1, uint32_t& a2, uint32_t& a3,
                                     uint32_t addr) {
    asm volatile("ldmatrix.sync.aligned.m8n8.x4.shared.b16 {%0,%1,%2,%3}, [%4];"
                 : "=r"(a0), "=r"(a1), "=r"(a2), "=r"(a3) : "r"(addr));
}
__device__ __forceinline__ void ldmBT4(uint32_t& b0, uint32_t& b1, uint32_t& b2, uint32_t& b3,
                                       uint32_t addr) {
    asm volatile("ldmatrix.sync.aligned.m8n8.x4.trans.shared.b16 {%0,%1,%2,%3}, [%4];"
                 : "=r"(b0), "=r"(b1), "=r"(b2), "=r"(b3) : "r"(addr));
}
__device__ __forceinline__ void mma16816(float* c, uint32_t a0, uint32_t a1, uint32_t a2,
                                         uint32_t a3, uint32_t b0, uint32_t b1) {
    asm volatile("mma.sync.aligned.m16n8k16.row.col.f32.bf16.bf16.f32 "
                 "{%0,%1,%2,%3}, {%4,%5,%6,%7}, {%8,%9}, {%0,%1,%2,%3};"
                 : "+f"(c[0]), "+f"(c[1]), "+f"(c[2]), "+f"(c[3])
                 : "r"(a0), "r"(a1), "r"(a2), "r"(a3), "r"(b0), "r"(b1));
}

// ---------------- GEMM body: B register-resident HMMA --------------------------
template<typename IT, typename WT>
__device__ __forceinline__ void gemm_body(
    int bid, __nv_bfloat16* smb,
    const IT* __restrict__ A, const WT* __restrict__ W,
    __nv_bfloat16* __restrict__ HB, int n)
{
    __nv_bfloat16* wsm = smb;             // [DD][AS]
    __nv_bfloat16* asmem = smb + DD * AS; // [GR][AS]

    const int tid  = threadIdx.x;
    const int lane = tid & 31;
    const int w    = tid >> 5;
    const int row0 = bid * GR;

    if (sizeof(WT) == 4) {
        for (int i = tid * 4; i < DD * DD; i += GT * 4) {
            float4 v = *(const float4*)&((const float*)W)[i];
            int k = i >> 7, nn = i & 127;
            __nv_bfloat162* p = (__nv_bfloat162*)&wsm[k * AS + nn];
            p[0] = __floats2bfloat162_rn(v.x, v.y);
            p[1] = __floats2bfloat162_rn(v.z, v.w);
        }
    } else {
        for (int i = tid * 8; i < DD * DD; i += GT * 8) {
            uint4 v = *(const uint4*)&((const __nv_bfloat16*)W)[i];
            int k = i >> 7, nn = i & 127;
            *(uint4*)&wsm[k * AS + nn] = v;
        }
    }
    if (sizeof(IT) == 4) {
        for (int i = tid * 4; i < GR * DD; i += GT * 4) {
            int r = i >> 7, k = i & 127;
            float4 v = make_float4(0.f, 0.f, 0.f, 0.f);
            if (row0 + r < n) v = *(const float4*)&((const float*)A)[(size_t)(row0 + r) * DD + k];
            __nv_bfloat162* p = (__nv_bfloat162*)&asmem[r * AS + k];
            p[0] = __floats2bfloat162_rn(v.x, v.y);
            p[1] = __floats2bfloat162_rn(v.z, v.w);
        }
    } else {
        for (int i = tid * 8; i < GR * DD; i += GT * 8) {
            int r = i >> 7, k = i & 127;
            uint4 v = make_uint4(0u, 0u, 0u, 0u);
            if (row0 + r < n) v = *(const uint4*)&((const __nv_bfloat16*)A)[(size_t)(row0 + r) * DD + k];
            *(uint4*)&asmem[r * AS + k] = v;
        }
    }
    __syncthreads();

    const int group = w >> 2;
    const int strip = w & 3;
    const int col0  = strip * 32;
    const int g = lane >> 2, t = lane & 3;

    uint32_t bf[8][8];
    {
        const int brow = lane & 15;
        const int bco  = (lane >> 4) * 8;
        #pragma unroll
        for (int kc = 0; kc < 8; kc++) {
            uint32_t ad0 = s2u(&wsm[(kc * 16 + brow) * AS + col0 + bco]);
            ldmBT4(bf[kc][0], bf[kc][1], bf[kc][2], bf[kc][3], ad0);
            uint32_t ad1 = s2u(&wsm[(kc * 16 + brow) * AS + col0 + 16 + bco]);
            ldmBT4(bf[kc][4], bf[kc][5], bf[kc][6], bf[kc][7], ad1);
        }
    }

    const int alrow = (lane & 15);
    const int acol  = (lane >> 4) * 8;

    #pragma unroll
    for (int rt = 0; rt < 4; rt++) {
        const int rbase = group * 64 + rt * 16;
        const uint32_t a_base = s2u(&asmem[(rbase + alrow) * AS + acol]);

        float acc[4][4];
        #pragma unroll
        for (int nt = 0; nt < 4; nt++)
            #pragma unroll
            for (int j = 0; j < 4; j++) acc[nt][j] = 0.f;

        #pragma unroll
        for (int kc = 0; kc < 8; kc++) {
            uint32_t a0, a1, a2, a3;
            ldmA(a0, a1, a2, a3, a_base + kc * 32);
            #pragma unroll
            for (int nt = 0; nt < 4; nt++)
                mma16816(acc[nt], a0, a1, a2, a3, bf[kc][nt * 2], bf[kc][nt * 2 + 1]);
        }

        const int r1 = row0 + rbase + g;
        const int r2 = r1 + 8;
        #pragma unroll
        for (int nt = 0; nt < 4; nt++) {
            int col = col0 + nt * 8 + t * 2;
            if (r1 < n)
                *(__nv_bfloat162*)&HB[(size_t)r1 * DD + col] =
                    __floats2bfloat162_rn(acc[nt][0], acc[nt][1]);
            if (r2 < n)
                *(__nv_bfloat162*)&HB[(size_t)r2 * DD + col] =
                    __floats2bfloat162_rn(acc[nt][2], acc[nt][3]);
        }
    }
}

// ---------------- fat kernel: gemm1 blocks + degree-count blocks ---------------
__global__ void __launch_bounds__(GT, 2)
k_fat_gemm_count(const float* __restrict__ A, const float* __restrict__ W,
                 __nv_bfloat16* __restrict__ HB, int n,
                 const int* __restrict__ dst, int* __restrict__ cnt, int gemm_blocks) {
    extern __shared__ __nv_bfloat16 smb[];
    if ((int)blockIdx.x < gemm_blocks) {
        gemm_body<float, float>(blockIdx.x, smb, A, W, HB, n);
    } else {
        int e = (blockIdx.x - gemm_blocks) * blockDim.x + threadIdx.x;
        if (e < NE) atomicAdd(&cnt[dst[e]], 1);
    }
}

// ---------------- plain GEMM kernel (layer 2: bf16 A, bf16 W) ------------------
__global__ void __launch_bounds__(GT, 2)
k_gemm_bb(const __nv_bfloat16* __restrict__ A, const __nv_bfloat16* __restrict__ W,
          __nv_bfloat16* __restrict__ HB, int n) {
    extern __shared__ __nv_bfloat16 smb[];
    gemm_body<__nv_bfloat16, __nv_bfloat16>(blockIdx.x, smb, A, W, HB, n);
}

// ---------------- W2 fp32 -> bf16 global ----------------
__global__ void k_wconv(const float* __restrict__ W, __nv_bfloat16* __restrict__ WB) {
    int i = (blockIdx.x * blockDim.x + threadIdx.x) * 4;
    if (i < DD * DD) {
        float4 v = *(const float4*)&W[i];
        __nv_bfloat162* p = (__nv_bfloat162*)&WB[i];
        p[0] = __floats2bfloat162_rn(v.x, v.y);
        p[1] = __floats2bfloat162_rn(v.z, v.w);
    }
}

// ---------------- single-block scan: padded offs, cursor, inv, dummy fill ------
__global__ void __launch_bounds__(SCAN_T)
k_scan(const int* __restrict__ cnt, int* __restrict__ offs,
       int* __restrict__ cursor, float* __restrict__ inv) {
    __shared__ int ssum[SCAN_T];
    int t = threadIdx.x;
    int c0 = t * SCAN_CH;
    int c1 = min(c0 + SCAN_CH, NN);
    int s = 0;
    for (int i = c0; i < c1; i++) s += (cnt[i] + 3) & ~3;   // padded sizes
    ssum[t] = s;
    __syncthreads();
    for (int off = 1; off < SCAN_T; off <<= 1) {
        int u = (t >= off) ? ssum[t - off] : 0;
        __syncthreads();
        ssum[t] += u;
        __syncthreads();
    }
    int run = ssum[t] - s;   // exclusive prefix (padded)
    for (int i = c0; i < c1; i++) {
        int c = cnt[i];
        int cp = (c + 3) & ~3;
        offs[i] = run;
        cursor[i] = run;
        inv[i] = rsqrtf((float)c + 1.0f);
        for (int j = c; j < cp; j++) g_adj[run + j] = make_int2(0, 0);  // dummy slots
        run += cp;
    }
    if (t == SCAN_T - 1) offs[NN] = run;
}

// ---------------- scatter edges into CSR bins (byte offsets, coef) ------------
__global__ void k_scatter(const int* __restrict__ src, const int* __restrict__ dst,
                          const float* __restrict__ inv,
                          int* __restrict__ cursor) {
    int e = blockIdx.x * blockDim.x + threadIdx.x;
    if (e >= NE) return;
    int s = src[e], d = dst[e];
    int pos = atomicAdd(&cursor[d], 1);
    g_adj[pos] = make_int2(s << 8, __float_as_int(inv[s] * inv[d]));  // s*256 bytes
}

// ---------------- paired-edge aggregation core --------------------------------
// Warp handles node d. Lanes 0-15 = half 0, lanes 16-31 = half 1.
// Each half processes alternate CSR slots; lane covers 16 bytes (8 cols) of row.
// acc[8] per lane; halves combined by shfl_xor(16) at the end.
__device__ __forceinline__ void fma8(float* acc, uint4 r, float c) {
    float2 f;
    f = __bfloat1622float2(*(__nv_bfloat162*)&r.x); acc[0] += c * f.x; acc[1] += c * f.y;
    f = __bfloat1622float2(*(__nv_bfloat162*)&r.y); acc[2] += c * f.x; acc[3] += c * f.y;
    f = __bfloat1622float2(*(__nv_bfloat162*)&r.z); acc[4] += c * f.x; acc[5] += c * f.y;
    f = __bfloat1622float2(*(__nv_bfloat162*)&r.w); acc[6] += c * f.x; acc[7] += c * f.y;
}

__device__ __forceinline__ void agg_node_pair(int d, int lane, float* acc) {
    const int half = lane >> 4;
    const int loff = (lane & 15) * 16;       // byte offset within row
    const int beg = g_offs[d];
    const int end = g_offs[d + 1];           // beg..end multiple of 4
    const char* hb = (const char*)g_hb;

    float invd = g_inv[d];
    float selfc = half ? 0.f : invd * invd;
    #pragma unroll
    for (int j = 0; j < 8; j++) acc[j] = 0.f;
    uint4 sr = *(const uint4*)(hb + d * 256 + loff);
    fma8(acc, sr, selfc);

    const int2* ap = g_adj + beg + half;     // this half's first slot
    for (int i = beg; i < end; i += 4, ap += 4) {
        int2 e0 = __ldg(ap);
        int2 e1 = __ldg(ap + 2);
        uint4 r0 = *(const uint4*)(hb + e0.x + loff);
        uint4 r1 = *(const uint4*)(hb + e1.x + loff);
        fma8(acc, r0, __int_as_float(e0.y));
        fma8(acc, r1, __int_as_float(e1.y));
    }

    #pragma unroll
    for (int j = 0; j < 8; j++)
        acc[j] += __shfl_xor_sync(0xFFFFFFFFu, acc[j], 16);
}

// ---------------- layer 1: ab = bf16(relu(aggregate + b1)) ----------------
__global__ void __launch_bounds__(256)
k_edge1(const float* __restrict__ b, __nv_bfloat16* __restrict__ out) {
    int warp = (blockIdx.x * blockDim.x + threadIdx.x) >> 5;
    if (warp >= NN) return;
    int lane = threadIdx.x & 31;
    float acc[8];
    agg_node_pair(warp, lane, acc);
    if (lane < 16) {
        float4 b0 = ((const float4*)b)[lane * 2];
        float4 b1 = ((const float4*)b)[lane * 2 + 1];
        uint4 ob;
        __nv_bfloat162 p;
        p = __floats2bfloat162_rn(fmaxf(acc[0] + b0.x, 0.f), fmaxf(acc[1] + b0.y, 0.f));
        ob.x = *(unsigned int*)&p;
        p = __floats2bfloat162_rn(fmaxf(acc[2] + b0.z, 0.f), fmaxf(acc[3] + b0.w, 0.f));
        ob.y = *(unsigned int*)&p;
        p = __floats2bfloat162_rn(fmaxf(acc[4] + b1.x, 0.f), fmaxf(acc[5] + b1.y, 0.f));
        ob.z = *(unsigned int*)&p;
        p = __floats2bfloat162_rn(fmaxf(acc[6] + b1.z, 0.f), fmaxf(acc[7] + b1.w, 0.f));
        ob.w = *(unsigned int*)&p;
        *(uint4*)((char*)out + (size_t)warp * 256 + lane * 16) = ob;
    }
}

// ---------------- layer 2: pool += relu(aggregate + b2); also zero cnt --------
__global__ void __launch_bounds__(256)
k_edge2_pool(const float* __restrict__ b, float* __restrict__ pool,
             int* __restrict__ cnt) {
    __shared__ float ps[DD];
    int tid = threadIdx.x;
    if (tid < DD) ps[tid] = 0.0f;
    __syncthreads();

    int gt = blockIdx.x * blockDim.x + tid;
    if (gt < NN) cnt[gt] = 0;    // reset for next graph replay

    int warp = gt >> 5;
    int lane = tid & 31;
    if (warp < NN) {
        float acc[8];
        agg_node_pair(warp, lane, acc);
        if (lane < 16) {
            float4 b0 = ((const float4*)b)[lane * 2];
            float4 b1 = ((const float4*)b)[lane * 2 + 1];
            float bb[8] = {b0.x, b0.y, b0.z, b0.w, b1.x, b1.y, b1.z, b1.w};
            #pragma unroll
            for (int j = 0; j < 8; j++)
                atomicAdd(&ps[lane * 8 + j], fmaxf(acc[j] + bb[j], 0.f));
        }
    }
    __syncthreads();
    if (tid < DD) atomicAdd(&pool[tid], ps[tid]);
}

// ---------------- finalize: logits + log_softmax; also zero pool ----------------
__global__ void k_finalize(float* __restrict__ pool, const float* __restrict__ Wc,
                           const float* __restrict__ bc, float* __restrict__ out) {
    int t = threadIdx.x;             // 0..31
    float l0 = 0.f, l1 = 0.f;
    const float invn = 1.0f / (float)NN;
    #pragma unroll
    for (int j = 0; j < 4; j++) {
        int c = t * 4 + j;
        float g = pool[c] * invn;
        l0 += g * Wc[c * NC + 0];
        l1 += g * Wc[c * NC + 1];
        pool[c] = 0.0f;              // reset for next graph replay
    }
    #pragma unroll
    for (int o = 16; o > 0; o >>= 1) {
        l0 += __shfl_down_sync(0xFFFFFFFFu, l0, o);
        l1 += __shfl_down_sync(0xFFFFFFFFu, l1, o);
    }
    if (t == 0) {
        l0 += bc[0];
        l1 += bc[1];
        float m = fmaxf(l0, l1);
        float lse = m + logf(expf(l0 - m) + expf(l1 - m));
        out[0] = l0 - lse;
        out[1] = l1 - lse;
    }
}

// ---------------- launch ----------------
extern "C" void kernel_launch(void* const* d_in, const int* in_sizes, int n_in,
                              void* d_out, int out_size) {
    const float* x  = (const float*)d_in[0];
    const int*   ei = (const int*)d_in[1];
    const float* W1 = (const float*)d_in[2];
    const float* b1 = (const float*)d_in[3];
    const float* W2 = (const float*)d_in[4];
    const float* b2 = (const float*)d_in[5];
    const float* Wc = (const float*)d_in[6];
    const float* bc = (const float*)d_in[7];
    float* out = (float*)d_out;

    const int* src = ei;
    const int* dst = ei + NE;

    int *cnt, *offs, *cursor;
    float *inv, *pool;
    __nv_bfloat16 *hb, *ab, *wb;
    cudaGetSymbolAddress((void**)&cnt,    g_cnt);
    cudaGetSymbolAddress((void**)&offs,   g_offs);
    cudaGetSymbolAddress((void**)&cursor, g_cursor);
    cudaGetSymbolAddress((void**)&inv,    g_inv);
    cudaGetSymbolAddress((void**)&hb,     g_hb);
    cudaGetSymbolAddress((void**)&ab,     g_ab);
    cudaGetSymbolAddress((void**)&wb,     g_wb);
    cudaGetSymbolAddress((void**)&pool,   g_pool);

    const int smem = (DD + GR) * AS * (int)sizeof(__nv_bfloat16);
    cudaFuncSetAttribute(k_fat_gemm_count, cudaFuncAttributeMaxDynamicSharedMemorySize, smem);
    cudaFuncSetAttribute(k_gemm_bb, cudaFuncAttributeMaxDynamicSharedMemorySize, smem);

    const int gemm_grid  = (NN + GR - 1) / GR;
    const int count_grid = (NE + GT - 1) / GT;
    const int edge_grid  = (NN * 32 + 255) / 256;

    // 0: fat = layer-1 GEMM + degree count
    k_fat_gemm_count<<<gemm_grid + count_grid, GT, smem>>>(x, W1, hb, NN, dst, cnt, gemm_grid);
    // 1-2: CSR build (padded)
    k_scan<<<1, SCAN_T>>>(cnt, offs, cursor, inv);
    k_scatter<<<(NE + 255) / 256, 256>>>(src, dst, inv, cursor);
    // 3: layer-1 aggregation  <-- ncu captures this launch
    k_edge1<<<edge_grid, 256>>>(b1, ab);
    // 4: W2 -> bf16
    k_wconv<<<(DD * DD / 4 + 255) / 256, 256>>>(W2, wb);
    // 5: layer-2 GEMM (bf16 x bf16)
    k_gemm_bb<<<gemm_grid, GT, smem>>>(ab, wb, hb, NN);
    // 6: layer-2 aggregation + pool (also resets cnt)
    k_edge2_pool<<<edge_grid, 256>>>(b2, pool, cnt);
    // 7: classifier + log_softmax (also resets pool)
    k_finalize<<<1, 32>>>(pool, Wc, bc, out);
}

// round 15
// speedup vs baseline: 1.2645x; 1.2645x over previous
#include <cuda_runtime.h>
#include <cuda_bf16.h>
#include <math.h>
#include <stdint.h>

// Problem constants
#define NN 50000
#define NE 800000
#define DD 128
#define NC 2
#define SCAN_T 1024
#define SCAN_CH 49          // ceil(NN / SCAN_T)
#define AS 136              // smem row stride (bf16) for GEMM
#define GR 128              // rows per GEMM block
#define GT 256              // threads per GEMM block
#define ADJ_CAP (NE + 3 * NN)   // CSR padded to multiple of 4 per node

// ---------------- scratch (static device memory; no allocation) ----------------
__device__ int   g_cnt[NN];          // in-degree -- zeroed by edge2 tail
__device__ int   g_offs[NN + 1];     // CSR row offsets (padded to x4)
__device__ int   g_cursor[NN];       // scatter cursors
__device__ __align__(16) int2 g_adj[ADJ_CAP];  // (src byte-offset, coef bits)
__device__ float g_inv[NN];          // deg^{-1/2}
__device__ __align__(16) __nv_bfloat16 g_hb[NN * DD];  // GEMM output (bf16)
__device__ __align__(16) __nv_bfloat16 g_ab[NN * DD];  // post-ReLU activations
__device__ __align__(16) __nv_bfloat16 g_wb[DD * DD];  // W2 pre-converted bf16
__device__ float g_pool[DD];         // pool sums -- zeroed by finalize tail

// ---------------- PTX helpers ----------------
__device__ __forceinline__ uint32_t s2u(const void* p) {
    uint32_t a;
    asm("{ .reg .u64 t; cvta.to.shared.u64 t, %1; cvt.u32.u64 %0, t; }"
        : "=r"(a) : "l"(p));
    return a;
}
__device__ __forceinline__ void ldmA(uint32_t& a0, uint32_t& a1, uint32_t& a2, uint32_t& a3,
                                     uint32_t addr) {
    asm volatile("ldmatrix.sync.aligned.m8n8.x4.shared.b16 {%0,%1,%2,%3}, [%4];"
                 : "=r"(a0), "=r"(a1), "=r"(a2), "=r"(a3) : "r"(addr));
}
__device__ __forceinline__ void ldmBT4(uint32_t& b0, uint32_t& b1, uint32_t& b2, uint32_t& b3,
                                       uint32_t addr) {
    asm volatile("ldmatrix.sync.aligned.m8n8.x4.trans.shared.b16 {%0,%1,%2,%3}, [%4];"
                 : "=r"(b0), "=r"(b1), "=r"(b2), "=r"(b3) : "r"(addr));
}
__device__ __forceinline__ void mma16816(float* c, uint32_t a0, uint32_t a1, uint32_t a2,
                                         uint32_t a3, uint32_t b0, uint32_t b1) {
    asm volatile("mma.sync.aligned.m16n8k16.row.col.f32.bf16.bf16.f32 "
                 "{%0,%1,%2,%3}, {%4,%5,%6,%7}, {%8,%9}, {%0,%1,%2,%3};"
                 : "+f"(c[0]), "+f"(c[1]), "+f"(c[2]), "+f"(c[3])
                 : "r"(a0), "r"(a1), "r"(a2), "r"(a3), "r"(b0), "r"(b1));
}

// ---------------- GEMM body: B register-resident HMMA --------------------------
template<typename IT, typename WT>
__device__ __forceinline__ void gemm_body(
    int bid, __nv_bfloat16* smb,
    const IT* __restrict__ A, const WT* __restrict__ W,
    __nv_bfloat16* __restrict__ HB, int n)
{
    __nv_bfloat16* wsm = smb;             // [DD][AS]
    __nv_bfloat16* asmem = smb + DD * AS; // [GR][AS]

    const int tid  = threadIdx.x;
    const int lane = tid & 31;
    const int w    = tid >> 5;
    const int row0 = bid * GR;

    if (sizeof(WT) == 4) {
        for (int i = tid * 4; i < DD * DD; i += GT * 4) {
            float4 v = *(const float4*)&((const float*)W)[i];
            int k = i >> 7, nn = i & 127;
            __nv_bfloat162* p = (__nv_bfloat162*)&wsm[k * AS + nn];
            p[0] = __floats2bfloat162_rn(v.x, v.y);
            p[1] = __floats2bfloat162_rn(v.z, v.w);
        }
    } else {
        for (int i = tid * 8; i < DD * DD; i += GT * 8) {
            uint4 v = *(const uint4*)&((const __nv_bfloat16*)W)[i];
            int k = i >> 7, nn = i & 127;
            *(uint4*)&wsm[k * AS + nn] = v;
        }
    }
    if (sizeof(IT) == 4) {
        for (int i = tid * 4; i < GR * DD; i += GT * 4) {
            int r = i >> 7, k = i & 127;
            float4 v = make_float4(0.f, 0.f, 0.f, 0.f);
            if (row0 + r < n) v = *(const float4*)&((const float*)A)[(size_t)(row0 + r) * DD + k];
            __nv_bfloat162* p = (__nv_bfloat162*)&asmem[r * AS + k];
            p[0] = __floats2bfloat162_rn(v.x, v.y);
            p[1] = __floats2bfloat162_rn(v.z, v.w);
        }
    } else {
        for (int i = tid * 8; i < GR * DD; i += GT * 8) {
            int r = i >> 7, k = i & 127;
            uint4 v = make_uint4(0u, 0u, 0u, 0u);
            if (row0 + r < n) v = *(const uint4*)&((const __nv_bfloat16*)A)[(size_t)(row0 + r) * DD + k];
            *(uint4*)&asmem[r * AS + k] = v;
        }
    }
    __syncthreads();

    const int group = w >> 2;
    const int strip = w & 3;
    const int col0  = strip * 32;
    const int g = lane >> 2, t = lane & 3;

    uint32_t bf[8][8];
    {
        const int brow = lane & 15;
        const int bco  = (lane >> 4) * 8;
        #pragma unroll
        for (int kc = 0; kc < 8; kc++) {
            uint32_t ad0 = s2u(&wsm[(kc * 16 + brow) * AS + col0 + bco]);
            ldmBT4(bf[kc][0], bf[kc][1], bf[kc][2], bf[kc][3], ad0);
            uint32_t ad1 = s2u(&wsm[(kc * 16 + brow) * AS + col0 + 16 + bco]);
            ldmBT4(bf[kc][4], bf[kc][5], bf[kc][6], bf[kc][7], ad1);
        }
    }

    const int alrow = (lane & 15);
    const int acol  = (lane >> 4) * 8;

    #pragma unroll
    for (int rt = 0; rt < 4; rt++) {
        const int rbase = group * 64 + rt * 16;
        const uint32_t a_base = s2u(&asmem[(rbase + alrow) * AS + acol]);

        float acc[4][4];
        #pragma unroll
        for (int nt = 0; nt < 4; nt++)
            #pragma unroll
            for (int j = 0; j < 4; j++) acc[nt][j] = 0.f;

        #pragma unroll
        for (int kc = 0; kc < 8; kc++) {
            uint32_t a0, a1, a2, a3;
            ldmA(a0, a1, a2, a3, a_base + kc * 32);
            #pragma unroll
            for (int nt = 0; nt < 4; nt++)
                mma16816(acc[nt], a0, a1, a2, a3, bf[kc][nt * 2], bf[kc][nt * 2 + 1]);
        }

        const int r1 = row0 + rbase + g;
        const int r2 = r1 + 8;
        #pragma unroll
        for (int nt = 0; nt < 4; nt++) {
            int col = col0 + nt * 8 + t * 2;
            if (r1 < n)
                *(__nv_bfloat162*)&HB[(size_t)r1 * DD + col] =
                    __floats2bfloat162_rn(acc[nt][0], acc[nt][1]);
            if (r2 < n)
                *(__nv_bfloat162*)&HB[(size_t)r2 * DD + col] =
                    __floats2bfloat162_rn(acc[nt][2], acc[nt][3]);
        }
    }
}

// ---------------- fat kernel: gemm1 blocks + degree-count blocks ---------------
__global__ void __launch_bounds__(GT, 2)
k_fat_gemm_count(const float* __restrict__ A, const float* __restrict__ W,
                 __nv_bfloat16* __restrict__ HB, int n,
                 const int* __restrict__ dst, int* __restrict__ cnt, int gemm_blocks) {
    extern __shared__ __nv_bfloat16 smb[];
    if ((int)blockIdx.x < gemm_blocks) {
        gemm_body<float, float>(blockIdx.x, smb, A, W, HB, n);
    } else {
        int e = (blockIdx.x - gemm_blocks) * blockDim.x + threadIdx.x;
        if (e < NE) atomicAdd(&cnt[dst[e]], 1);
    }
}

// ---------------- plain GEMM kernel (layer 2: bf16 A, bf16 W) ------------------
__global__ void __launch_bounds__(GT, 2)
k_gemm_bb(const __nv_bfloat16* __restrict__ A, const __nv_bfloat16* __restrict__ W,
          __nv_bfloat16* __restrict__ HB, int n) {
    extern __shared__ __nv_bfloat16 smb[];
    gemm_body<__nv_bfloat16, __nv_bfloat16>(blockIdx.x, smb, A, W, HB, n);
}

// ---------------- W2 fp32 -> bf16 global ----------------
__global__ void k_wconv(const float* __restrict__ W, __nv_bfloat16* __restrict__ WB) {
    int i = (blockIdx.x * blockDim.x + threadIdx.x) * 4;
    if (i < DD * DD) {
        float4 v = *(const float4*)&W[i];
        __nv_bfloat162* p = (__nv_bfloat162*)&WB[i];
        p[0] = __floats2bfloat162_rn(v.x, v.y);
        p[1] = __floats2bfloat162_rn(v.z, v.w);
    }
}

// ---------------- single-block scan: padded offs, cursor, inv (no fill) --------
__global__ void __launch_bounds__(SCAN_T)
k_scan(const int* __restrict__ cnt, int* __restrict__ offs,
       int* __restrict__ cursor, float* __restrict__ inv) {
    __shared__ int ssum[SCAN_T];
    int t = threadIdx.x;
    int c0 = t * SCAN_CH;
    int c1 = min(c0 + SCAN_CH, NN);
    int s = 0;
    for (int i = c0; i < c1; i++) s += (cnt[i] + 3) & ~3;   // padded sizes
    ssum[t] = s;
    __syncthreads();
    for (int off = 1; off < SCAN_T; off <<= 1) {
        int u = (t >= off) ? ssum[t - off] : 0;
        __syncthreads();
        ssum[t] += u;
        __syncthreads();
    }
    int run = ssum[t] - s;   // exclusive prefix (padded)
    for (int i = c0; i < c1; i++) {
        int c = cnt[i];
        offs[i] = run;
        cursor[i] = run;
        inv[i] = rsqrtf((float)c + 1.0f);
        run += (c + 3) & ~3;
    }
    if (t == SCAN_T - 1) offs[NN] = run;
}

// ---------------- scatter edges + grid-parallel pad fill ----------------------
// Blocks [0, scat_blocks): one thread per edge -> CSR slot (byte offset, coef).
// Blocks [scat_blocks, ...): one thread per node -> fill pad slots with (0, 0).
// Regions are disjoint ([offs, offs+cnt) vs [offs+cnt, offs+cp)) so both parts
// can run concurrently within this launch.
__global__ void k_scatter(const int* __restrict__ src, const int* __restrict__ dst,
                          const float* __restrict__ inv,
                          int* __restrict__ cursor,
                          const int* __restrict__ offs, const int* __restrict__ cnt,
                          int scat_blocks) {
    if ((int)blockIdx.x < scat_blocks) {
        int e = blockIdx.x * blockDim.x + threadIdx.x;
        if (e >= NE) return;
        int s = src[e], d = dst[e];
        int pos = atomicAdd(&cursor[d], 1);
        g_adj[pos] = make_int2(s << 8, __float_as_int(inv[s] * inv[d]));  // s*256 bytes
    } else {
        int d = (blockIdx.x - scat_blocks) * blockDim.x + threadIdx.x;
        if (d >= NN) return;
        int c = cnt[d];
        int cp = (c + 3) & ~3;
        int o = offs[d];
        for (int j = c; j < cp; j++)
            g_adj[o + j] = make_int2(0, 0);   // dummy: reads hb[0..], coef 0
    }
}

// ---------------- paired-edge aggregation core --------------------------------
// Warp handles node d. Lanes 0-15 = half 0, lanes 16-31 = half 1.
// Each half processes alternate CSR slots; lane covers 16 bytes (8 cols) of row.
// acc[8] per lane; halves combined by shfl_xor(16) at the end.
__device__ __forceinline__ void fma8(float* acc, uint4 r, float c) {
    float2 f;
    f = __bfloat1622float2(*(__nv_bfloat162*)&r.x); acc[0] += c * f.x; acc[1] += c * f.y;
    f = __bfloat1622float2(*(__nv_bfloat162*)&r.y); acc[2] += c * f.x; acc[3] += c * f.y;
    f = __bfloat1622float2(*(__nv_bfloat162*)&r.z); acc[4] += c * f.x; acc[5] += c * f.y;
    f = __bfloat1622float2(*(__nv_bfloat162*)&r.w); acc[6] += c * f.x; acc[7] += c * f.y;
}

__device__ __forceinline__ void agg_node_pair(int d, int lane, float* acc) {
    const int half = lane >> 4;
    const int loff = (lane & 15) * 16;       // byte offset within row
    const int beg = g_offs[d];
    const int end = g_offs[d + 1];           // beg..end multiple of 4
    const char* hb = (const char*)g_hb;

    float invd = g_inv[d];
    float selfc = half ? 0.f : invd * invd;
    #pragma unroll
    for (int j = 0; j < 8; j++) acc[j] = 0.f;
    uint4 sr = *(const uint4*)(hb + d * 256 + loff);
    fma8(acc, sr, selfc);

    const int2* ap = g_adj + beg + half;     // this half's first slot
    for (int i = beg; i < end; i += 4, ap += 4) {
        int2 e0 = __ldg(ap);
        int2 e1 = __ldg(ap + 2);
        uint4 r0 = *(const uint4*)(hb + e0.x + loff);
        uint4 r1 = *(const uint4*)(hb + e1.x + loff);
        fma8(acc, r0, __int_as_float(e0.y));
        fma8(acc, r1, __int_as_float(e1.y));
    }

    #pragma unroll
    for (int j = 0; j < 8; j++)
        acc[j] += __shfl_xor_sync(0xFFFFFFFFu, acc[j], 16);
}

// ---------------- layer 1: ab = bf16(relu(aggregate + b1)) ----------------
__global__ void __launch_bounds__(256)
k_edge1(const float* __restrict__ b, __nv_bfloat16* __restrict__ out) {
    int warp = (blockIdx.x * blockDim.x + threadIdx.x) >> 5;
    if (warp >= NN) return;
    int lane = threadIdx.x & 31;
    float acc[8];
    agg_node_pair(warp, lane, acc);
    if (lane < 16) {
        float4 b0 = ((const float4*)b)[lane * 2];
        float4 b1 = ((const float4*)b)[lane * 2 + 1];
        uint4 ob;
        __nv_bfloat162 p;
        p = __floats2bfloat162_rn(fmaxf(acc[0] + b0.x, 0.f), fmaxf(acc[1] + b0.y, 0.f));
        ob.x = *(unsigned int*)&p;
        p = __floats2bfloat162_rn(fmaxf(acc[2] + b0.z, 0.f), fmaxf(acc[3] + b0.w, 0.f));
        ob.y = *(unsigned int*)&p;
        p = __floats2bfloat162_rn(fmaxf(acc[4] + b1.x, 0.f), fmaxf(acc[5] + b1.y, 0.f));
        ob.z = *(unsigned int*)&p;
        p = __floats2bfloat162_rn(fmaxf(acc[6] + b1.z, 0.f), fmaxf(acc[7] + b1.w, 0.f));
        ob.w = *(unsigned int*)&p;
        *(uint4*)((char*)out + (size_t)warp * 256 + lane * 16) = ob;
    }
}

// ---------------- layer 2: pool += relu(aggregate + b2); also zero cnt --------
__global__ void __launch_bounds__(256)
k_edge2_pool(const float* __restrict__ b, float* __restrict__ pool,
             int* __restrict__ cnt) {
    __shared__ float ps[DD];
    int tid = threadIdx.x;
    if (tid < DD) ps[tid] = 0.0f;
    __syncthreads();

    int gt = blockIdx.x * blockDim.x + tid;
    if (gt < NN) cnt[gt] = 0;    // reset for next graph replay

    int warp = gt >> 5;
    int lane = tid & 31;
    if (warp < NN) {
        float acc[8];
        agg_node_pair(warp, lane, acc);
        if (lane < 16) {
            float4 b0 = ((const float4*)b)[lane * 2];
            float4 b1 = ((const float4*)b)[lane * 2 + 1];
            float bb[8] = {b0.x, b0.y, b0.z, b0.w, b1.x, b1.y, b1.z, b1.w};
            #pragma unroll
            for (int j = 0; j < 8; j++)
                atomicAdd(&ps[lane * 8 + j], fmaxf(acc[j] + bb[j], 0.f));
        }
    }
    __syncthreads();
    if (tid < DD) atomicAdd(&pool[tid], ps[tid]);
}

// ---------------- finalize: logits + log_softmax; also zero pool ----------------
__global__ void k_finalize(float* __restrict__ pool, const float* __restrict__ Wc,
                           const float* __restrict__ bc, float* __restrict__ out) {
    int t = threadIdx.x;             // 0..31
    float l0 = 0.f, l1 = 0.f;
    const float invn = 1.0f / (float)NN;
    #pragma unroll
    for (int j = 0; j < 4; j++) {
        int c = t * 4 + j;
        float g = pool[c] * invn;
        l0 += g * Wc[c * NC + 0];
        l1 += g * Wc[c * NC + 1];
        pool[c] = 0.0f;              // reset for next graph replay
    }
    #pragma unroll
    for (int o = 16; o > 0; o >>= 1) {
        l0 += __shfl_down_sync(0xFFFFFFFFu, l0, o);
        l1 += __shfl_down_sync(0xFFFFFFFFu, l1, o);
    }
    if (t == 0) {
        l0 += bc[0];
        l1 += bc[1];
        float m = fmaxf(l0, l1);
        float lse = m + logf(expf(l0 - m) + expf(l1 - m));
        out[0] = l0 - lse;
        out[1] = l1 - lse;
    }
}

// ---------------- launch ----------------
extern "C" void kernel_launch(void* const* d_in, const int* in_sizes, int n_in,
                              void* d_out, int out_size) {
    const float* x  = (const float*)d_in[0];
    const int*   ei = (const int*)d_in[1];
    const float* W1 = (const float*)d_in[2];
    const float* b1 = (const float*)d_in[3];
    const float* W2 = (const float*)d_in[4];
    const float* b2 = (const float*)d_in[5];
    const float* Wc = (const float*)d_in[6];
    const float* bc = (const float*)d_in[7];
    float* out = (float*)d_out;

    const int* src = ei;
    const int* dst = ei + NE;

    int *cnt, *offs, *cursor;
    float *inv, *pool;
    __nv_bfloat16 *hb, *ab, *wb;
    cudaGetSymbolAddress((void**)&cnt,    g_cnt);
    cudaGetSymbolAddress((void**)&offs,   g_offs);
    cudaGetSymbolAddress((void**)&cursor, g_cursor);
    cudaGetSymbolAddress((void**)&inv,    g_inv);
    cudaGetSymbolAddress((void**)&hb,     g_hb);
    cudaGetSymbolAddress((void**)&ab,     g_ab);
    cudaGetSymbolAddress((void**)&wb,     g_wb);
    cudaGetSymbolAddress((void**)&pool,   g_pool);

    const int smem = (DD + GR) * AS * (int)sizeof(__nv_bfloat16);
    cudaFuncSetAttribute(k_fat_gemm_count, cudaFuncAttributeMaxDynamicSharedMemorySize, smem);
    cudaFuncSetAttribute(k_gemm_bb, cudaFuncAttributeMaxDynamicSharedMemorySize, smem);

    const int gemm_grid   = (NN + GR - 1) / GR;
    const int count_grid  = (NE + GT - 1) / GT;
    const int edge_grid   = (NN * 32 + 255) / 256;
    const int scat_blocks = (NE + 255) / 256;
    const int pad_blocks  = (NN + 255) / 256;

    // 0: fat = layer-1 GEMM + degree count
    k_fat_gemm_count<<<gemm_grid + count_grid, GT, smem>>>(x, W1, hb, NN, dst, cnt, gemm_grid);
    // 1: padded CSR offsets (single block, minimal serial work)
    k_scan<<<1, SCAN_T>>>(cnt, offs, cursor, inv);
    // 2: scatter edges + grid-parallel pad fill (disjoint regions, one launch)
    k_scatter<<<scat_blocks + pad_blocks, 256>>>(src, dst, inv, cursor, offs, cnt, scat_blocks);
    // 3: layer-1 aggregation  <-- ncu captures this launch
    k_edge1<<<edge_grid, 256>>>(b1, ab);
    // 4: W2 -> bf16
    k_wconv<<<(DD * DD / 4 + 255) / 256, 256>>>(W2, wb);
    // 5: layer-2 GEMM (bf16 x bf16)
    k_gemm_bb<<<gemm_grid, GT, smem>>>(ab, wb, hb, NN);
    // 6: layer-2 aggregation + pool (also resets cnt)
    k_edge2_pool<<<edge_grid, 256>>>(b2, pool, cnt);
    // 7: classifier + log_softmax (also resets pool)
    k_finalize<<<1, 32>>>(pool, Wc, bc, out);
}

// round 16
// speedup vs baseline: 1.3298x; 1.0516x over previous
#include <cuda_runtime.h>
#include <cuda_bf16.h>
#include <math.h>
#include <stdint.h>

// Problem constants
#define NN 50000
#define NE 800000
#define DD 128
#define NC 2
#define SCAN_T 1024
#define SCAN_CH 49          // ceil(NN / SCAN_T)
#define AS 136              // smem row stride (bf16) for GEMM
#define GR 128              // rows per GEMM block
#define GT 256              // threads per GEMM block
#define ADJ_CAP (NE + 3 * NN)   // CSR padded to multiple of 4 per node

// ---------------- scratch (static device memory; no allocation) ----------------
__device__ int   g_cnt[NN];          // in-degree -- zeroed by edge2 tail
__device__ int   g_offs[NN + 1];     // CSR row offsets (padded to x4)
__device__ int   g_cursor[NN];       // scatter cursors
__device__ __align__(16) int2 g_adj[ADJ_CAP];  // (src byte-offset, coef bits)
__device__ float g_inv[NN];          // deg^{-1/2}
__device__ __align__(16) __nv_bfloat16 g_hb[NN * DD];  // GEMM output (bf16)
__device__ __align__(16) __nv_bfloat16 g_ab[NN * DD];  // post-ReLU activations
__device__ __align__(16) __nv_bfloat16 g_wb[DD * DD];  // W2 pre-converted bf16
__device__ float g_pool[DD];         // pool sums -- zeroed by finalize tail

// ---------------- PTX helpers ----------------
__device__ __forceinline__ uint32_t s2u(const void* p) {
    uint32_t a;
    asm("{ .reg .u64 t; cvta.to.shared.u64 t, %1; cvt.u32.u64 %0, t; }"
        : "=r"(a) : "l"(p));
    return a;
}
__device__ __forceinline__ void ldmA(uint32_t& a0, uint32_t& a1, uint32_t& a2, uint32_t& a3,
                                     uint32_t addr) {
    asm volatile("ldmatrix.sync.aligned.m8n8.x4.shared.b16 {%0,%1,%2,%3}, [%4];"
                 : "=r"(a0), "=r"(a1), "=r"(a2), "=r"(a3) : "r"(addr));
}
__device__ __forceinline__ void ldmBT4(uint32_t& b0, uint32_t& b1, uint32_t& b2, uint32_t& b3,
                                       uint32_t addr) {
    asm volatile("ldmatrix.sync.aligned.m8n8.x4.trans.shared.b16 {%0,%1,%2,%3}, [%4];"
                 : "=r"(b0), "=r"(b1), "=r"(b2), "=r"(b3) : "r"(addr));
}
__device__ __forceinline__ void mma16816(float* c, uint32_t a0, uint32_t a1, uint32_t a2,
                                         uint32_t a3, uint32_t b0, uint32_t b1) {
    asm volatile("mma.sync.aligned.m16n8k16.row.col.f32.bf16.bf16.f32 "
                 "{%0,%1,%2,%3}, {%4,%5,%6,%7}, {%8,%9}, {%0,%1,%2,%3};"
                 : "+f"(c[0]), "+f"(c[1]), "+f"(c[2]), "+f"(c[3])
                 : "r"(a0), "r"(a1), "r"(a2), "r"(a3), "r"(b0), "r"(b1));
}

// ---------------- GEMM body: B register-resident HMMA --------------------------
// Staging issues 8 independent LDG.128 per thread BEFORE converts/stores (MLP).
template<typename IT, typename WT>
__device__ __forceinline__ void gemm_body(
    int bid, __nv_bfloat16* smb,
    const IT* __restrict__ A, const WT* __restrict__ W,
    __nv_bfloat16* __restrict__ HB, int n)
{
    __nv_bfloat16* wsm = smb;             // [DD][AS]
    __nv_bfloat16* asmem = smb + DD * AS; // [GR][AS]

    const int tid  = threadIdx.x;
    const int lane = tid & 31;
    const int w    = tid >> 5;
    const int row0 = bid * GR;

    // ---- W -> bf16 smem (batched loads) ----
    if (sizeof(WT) == 4) {
        const float* Wf = (const float*)W;
        #pragma unroll
        for (int half = 0; half < 2; half++) {
            float4 v[8];
            #pragma unroll
            for (int j = 0; j < 8; j++)
                v[j] = *(const float4*)&Wf[(tid + (half * 8 + j) * GT) * 4];
            #pragma unroll
            for (int j = 0; j < 8; j++) {
                int i = (tid + (half * 8 + j) * GT) * 4;
                int k = i >> 7, nn = i & 127;
                __nv_bfloat162* p = (__nv_bfloat162*)&wsm[k * AS + nn];
                p[0] = __floats2bfloat162_rn(v[j].x, v[j].y);
                p[1] = __floats2bfloat162_rn(v[j].z, v[j].w);
            }
        }
    } else {
        const __nv_bfloat16* Wb = (const __nv_bfloat16*)W;
        uint4 v[8];
        #pragma unroll
        for (int j = 0; j < 8; j++)
            v[j] = *(const uint4*)&Wb[(tid + j * GT) * 8];
        #pragma unroll
        for (int j = 0; j < 8; j++) {
            int i = (tid + j * GT) * 8;
            int k = i >> 7, nn = i & 127;
            *(uint4*)&wsm[k * AS + nn] = v[j];
        }
    }
    // ---- A rows -> bf16 smem (batched loads) ----
    if (sizeof(IT) == 4) {
        const float* Af = (const float*)A;
        #pragma unroll
        for (int half = 0; half < 2; half++) {
            float4 v[8];
            #pragma unroll
            for (int j = 0; j < 8; j++) {
                int i = (tid + (half * 8 + j) * GT) * 4;
                int r = i >> 7;
                v[j] = make_float4(0.f, 0.f, 0.f, 0.f);
                if (row0 + r < n) v[j] = *(const float4*)&Af[(size_t)(row0 + r) * DD + (i & 127)];
            }
            #pragma unroll
            for (int j = 0; j < 8; j++) {
                int i = (tid + (half * 8 + j) * GT) * 4;
                int r = i >> 7, k = i & 127;
                __nv_bfloat162* p = (__nv_bfloat162*)&asmem[r * AS + k];
                p[0] = __floats2bfloat162_rn(v[j].x, v[j].y);
                p[1] = __floats2bfloat162_rn(v[j].z, v[j].w);
            }
        }
    } else {
        const __nv_bfloat16* Ab = (const __nv_bfloat16*)A;
        uint4 v[8];
        #pragma unroll
        for (int j = 0; j < 8; j++) {
            int i = (tid + j * GT) * 8;
            int r = i >> 7;
            v[j] = make_uint4(0u, 0u, 0u, 0u);
            if (row0 + r < n) v[j] = *(const uint4*)&Ab[(size_t)(row0 + r) * DD + (i & 127)];
        }
        #pragma unroll
        for (int j = 0; j < 8; j++) {
            int i = (tid + j * GT) * 8;
            int r = i >> 7, k = i & 127;
            *(uint4*)&asmem[r * AS + k] = v[j];
        }
    }
    __syncthreads();

    const int group = w >> 2;
    const int strip = w & 3;
    const int col0  = strip * 32;
    const int g = lane >> 2, t = lane & 3;

    uint32_t bf[8][8];
    {
        const int brow = lane & 15;
        const int bco  = (lane >> 4) * 8;
        #pragma unroll
        for (int kc = 0; kc < 8; kc++) {
            uint32_t ad0 = s2u(&wsm[(kc * 16 + brow) * AS + col0 + bco]);
            ldmBT4(bf[kc][0], bf[kc][1], bf[kc][2], bf[kc][3], ad0);
            uint32_t ad1 = s2u(&wsm[(kc * 16 + brow) * AS + col0 + 16 + bco]);
            ldmBT4(bf[kc][4], bf[kc][5], bf[kc][6], bf[kc][7], ad1);
        }
    }

    const int alrow = (lane & 15);
    const int acol  = (lane >> 4) * 8;

    #pragma unroll
    for (int rt = 0; rt < 4; rt++) {
        const int rbase = group * 64 + rt * 16;
        const uint32_t a_base = s2u(&asmem[(rbase + alrow) * AS + acol]);

        float acc[4][4];
        #pragma unroll
        for (int nt = 0; nt < 4; nt++)
            #pragma unroll
            for (int j = 0; j < 4; j++) acc[nt][j] = 0.f;

        #pragma unroll
        for (int kc = 0; kc < 8; kc++) {
            uint32_t a0, a1, a2, a3;
            ldmA(a0, a1, a2, a3, a_base + kc * 32);
            #pragma unroll
            for (int nt = 0; nt < 4; nt++)
                mma16816(acc[nt], a0, a1, a2, a3, bf[kc][nt * 2], bf[kc][nt * 2 + 1]);
        }

        const int r1 = row0 + rbase + g;
        const int r2 = r1 + 8;
        #pragma unroll
        for (int nt = 0; nt < 4; nt++) {
            int col = col0 + nt * 8 + t * 2;
            if (r1 < n)
                *(__nv_bfloat162*)&HB[(size_t)r1 * DD + col] =
                    __floats2bfloat162_rn(acc[nt][0], acc[nt][1]);
            if (r2 < n)
                *(__nv_bfloat162*)&HB[(size_t)r2 * DD + col] =
                    __floats2bfloat162_rn(acc[nt][2], acc[nt][3]);
        }
    }
}

// ---------------- fat kernel: gemm1 + degree-count + W2-convert blocks ---------
__global__ void __launch_bounds__(GT, 2)
k_fat_gemm_count(const float* __restrict__ A, const float* __restrict__ W,
                 __nv_bfloat16* __restrict__ HB, int n,
                 const int* __restrict__ dst, int* __restrict__ cnt,
                 const float* __restrict__ W2, __nv_bfloat16* __restrict__ WB,
                 int gemm_blocks, int count_blocks) {
    extern __shared__ __nv_bfloat16 smb[];
    int b = (int)blockIdx.x;
    if (b < gemm_blocks) {
        gemm_body<float, float>(b, smb, A, W, HB, n);
    } else if (b < gemm_blocks + count_blocks) {
        int e = (b - gemm_blocks) * blockDim.x + threadIdx.x;
        if (e < NE) atomicAdd(&cnt[dst[e]], 1);
    } else {
        int i = ((b - gemm_blocks - count_blocks) * blockDim.x + threadIdx.x) * 4;
        if (i < DD * DD) {
            float4 v = *(const float4*)&W2[i];
            __nv_bfloat162* p = (__nv_bfloat162*)&WB[i];
            p[0] = __floats2bfloat162_rn(v.x, v.y);
            p[1] = __floats2bfloat162_rn(v.z, v.w);
        }
    }
}

// ---------------- plain GEMM kernel (layer 2: bf16 A, bf16 W) ------------------
__global__ void __launch_bounds__(GT, 2)
k_gemm_bb(const __nv_bfloat16* __restrict__ A, const __nv_bfloat16* __restrict__ W,
          __nv_bfloat16* __restrict__ HB, int n) {
    extern __shared__ __nv_bfloat16 smb[];
    gemm_body<__nv_bfloat16, __nv_bfloat16>(blockIdx.x, smb, A, W, HB, n);
}

// ---------------- single-block scan: padded offs, cursor, inv (no fill) --------
__global__ void __launch_bounds__(SCAN_T)
k_scan(const int* __restrict__ cnt, int* __restrict__ offs,
       int* __restrict__ cursor, float* __restrict__ inv) {
    __shared__ int ssum[SCAN_T];
    int t = threadIdx.x;
    int c0 = t * SCAN_CH;
    int c1 = min(c0 + SCAN_CH, NN);
    int s = 0;
    for (int i = c0; i < c1; i++) s += (cnt[i] + 3) & ~3;   // padded sizes
    ssum[t] = s;
    __syncthreads();
    for (int off = 1; off < SCAN_T; off <<= 1) {
        int u = (t >= off) ? ssum[t - off] : 0;
        __syncthreads();
        ssum[t] += u;
        __syncthreads();
    }
    int run = ssum[t] - s;   // exclusive prefix (padded)
    for (int i = c0; i < c1; i++) {
        int c = cnt[i];
        offs[i] = run;
        cursor[i] = run;
        inv[i] = rsqrtf((float)c + 1.0f);
        run += (c + 3) & ~3;
    }
    if (t == SCAN_T - 1) offs[NN] = run;
}

// ---------------- scatter edges + grid-parallel pad fill ----------------------
__global__ void k_scatter(const int* __restrict__ src, const int* __restrict__ dst,
                          const float* __restrict__ inv,
                          int* __restrict__ cursor,
                          const int* __restrict__ offs, const int* __restrict__ cnt,
                          int scat_blocks) {
    if ((int)blockIdx.x < scat_blocks) {
        int e = blockIdx.x * blockDim.x + threadIdx.x;
        if (e >= NE) return;
        int s = src[e], d = dst[e];
        int pos = atomicAdd(&cursor[d], 1);
        g_adj[pos] = make_int2(s << 8, __float_as_int(inv[s] * inv[d]));  // s*256 bytes
    } else {
        int d = (blockIdx.x - scat_blocks) * blockDim.x + threadIdx.x;
        if (d >= NN) return;
        int c = cnt[d];
        int cp = (c + 3) & ~3;
        int o = offs[d];
        for (int j = c; j < cp; j++)
            g_adj[o + j] = make_int2(0, 0);   // dummy: reads hb[0..], coef 0
    }
}

// ---------------- paired-edge aggregation core --------------------------------
__device__ __forceinline__ void fma8(float* acc, uint4 r, float c) {
    float2 f;
    f = __bfloat1622float2(*(__nv_bfloat162*)&r.x); acc[0] += c * f.x; acc[1] += c * f.y;
    f = __bfloat1622float2(*(__nv_bfloat162*)&r.y); acc[2] += c * f.x; acc[3] += c * f.y;
    f = __bfloat1622float2(*(__nv_bfloat162*)&r.z); acc[4] += c * f.x; acc[5] += c * f.y;
    f = __bfloat1622float2(*(__nv_bfloat162*)&r.w); acc[6] += c * f.x; acc[7] += c * f.y;
}

__device__ __forceinline__ void agg_node_pair(int d, int lane, float* acc) {
    const int half = lane >> 4;
    const int loff = (lane & 15) * 16;       // byte offset within row
    const int beg = g_offs[d];
    const int end = g_offs[d + 1];           // beg..end multiple of 4
    const char* hb = (const char*)g_hb;

    float invd = g_inv[d];
    float selfc = half ? 0.f : invd * invd;
    #pragma unroll
    for (int j = 0; j < 8; j++) acc[j] = 0.f;
    uint4 sr = *(const uint4*)(hb + d * 256 + loff);
    fma8(acc, sr, selfc);

    const int2* ap = g_adj + beg + half;     // this half's first slot
    for (int i = beg; i < end; i += 4, ap += 4) {
        int2 e0 = __ldg(ap);
        int2 e1 = __ldg(ap + 2);
        uint4 r0 = *(const uint4*)(hb + e0.x + loff);
        uint4 r1 = *(const uint4*)(hb + e1.x + loff);
        fma8(acc, r0, __int_as_float(e0.y));
        fma8(acc, r1, __int_as_float(e1.y));
    }

    #pragma unroll
    for (int j = 0; j < 8; j++)
        acc[j] += __shfl_xor_sync(0xFFFFFFFFu, acc[j], 16);
}

// ---------------- layer 1: ab = bf16(relu(aggregate + b1)) ----------------
__global__ void __launch_bounds__(256)
k_edge1(const float* __restrict__ b, __nv_bfloat16* __restrict__ out) {
    int warp = (blockIdx.x * blockDim.x + threadIdx.x) >> 5;
    if (warp >= NN) return;
    int lane = threadIdx.x & 31;
    float acc[8];
    agg_node_pair(warp, lane, acc);
    if (lane < 16) {
        float4 b0 = ((const float4*)b)[lane * 2];
        float4 b1 = ((const float4*)b)[lane * 2 + 1];
        uint4 ob;
        __nv_bfloat162 p;
        p = __floats2bfloat162_rn(fmaxf(acc[0] + b0.x, 0.f), fmaxf(acc[1] + b0.y, 0.f));
        ob.x = *(unsigned int*)&p;
        p = __floats2bfloat162_rn(fmaxf(acc[2] + b0.z, 0.f), fmaxf(acc[3] + b0.w, 0.f));
        ob.y = *(unsigned int*)&p;
        p = __floats2bfloat162_rn(fmaxf(acc[4] + b1.x, 0.f), fmaxf(acc[5] + b1.y, 0.f));
        ob.z = *(unsigned int*)&p;
        p = __floats2bfloat162_rn(fmaxf(acc[6] + b1.z, 0.f), fmaxf(acc[7] + b1.w, 0.f));
        ob.w = *(unsigned int*)&p;
        *(uint4*)((char*)out + (size_t)warp * 256 + lane * 16) = ob;
    }
}

// ---------------- layer 2: pool += relu(aggregate + b2); also zero cnt --------
__global__ void __launch_bounds__(256)
k_edge2_pool(const float* __restrict__ b, float* __restrict__ pool,
             int* __restrict__ cnt) {
    __shared__ float ps[DD];
    int tid = threadIdx.x;
    if (tid < DD) ps[tid] = 0.0f;
    __syncthreads();

    int gt = blockIdx.x * blockDim.x + tid;
    if (gt < NN) cnt[gt] = 0;    // reset for next graph replay

    int warp = gt >> 5;
    int lane = tid & 31;
    if (warp < NN) {
        float acc[8];
        agg_node_pair(warp, lane, acc);
        if (lane < 16) {
            float4 b0 = ((const float4*)b)[lane * 2];
            float4 b1 = ((const float4*)b)[lane * 2 + 1];
            float bb[8] = {b0.x, b0.y, b0.z, b0.w, b1.x, b1.y, b1.z, b1.w};
            #pragma unroll
            for (int j = 0; j < 8; j++)
                atomicAdd(&ps[lane * 8 + j], fmaxf(acc[j] + bb[j], 0.f));
        }
    }
    __syncthreads();
    if (tid < DD) atomicAdd(&pool[tid], ps[tid]);
}

// ---------------- finalize: logits + log_softmax; also zero pool ----------------
__global__ void k_finalize(float* __restrict__ pool, const float* __restrict__ Wc,
                           const float* __restrict__ bc, float* __restrict__ out) {
    int t = threadIdx.x;             // 0..31
    float l0 = 0.f, l1 = 0.f;
    const float invn = 1.0f / (float)NN;
    #pragma unroll
    for (int j = 0; j < 4; j++) {
        int c = t * 4 + j;
        float g = pool[c] * invn;
        l0 += g * Wc[c * NC + 0];
        l1 += g * Wc[c * NC + 1];
        pool[c] = 0.0f;              // reset for next graph replay
    }
    #pragma unroll
    for (int o = 16; o > 0; o >>= 1) {
        l0 += __shfl_down_sync(0xFFFFFFFFu, l0, o);
        l1 += __shfl_down_sync(0xFFFFFFFFu, l1, o);
    }
    if (t == 0) {
        l0 += bc[0];
        l1 += bc[1];
        float m = fmaxf(l0, l1);
        float lse = m + logf(expf(l0 - m) + expf(l1 - m));
        out[0] = l0 - lse;
        out[1] = l1 - lse;
    }
}

// ---------------- launch ----------------
extern "C" void kernel_launch(void* const* d_in, const int* in_sizes, int n_in,
                              void* d_out, int out_size) {
    const float* x  = (const float*)d_in[0];
    const int*   ei = (const int*)d_in[1];
    const float* W1 = (const float*)d_in[2];
    const float* b1 = (const float*)d_in[3];
    const float* W2 = (const float*)d_in[4];
    const float* b2 = (const float*)d_in[5];
    const float* Wc = (const float*)d_in[6];
    const float* bc = (const float*)d_in[7];
    float* out = (float*)d_out;

    const int* src = ei;
    const int* dst = ei + NE;

    int *cnt, *offs, *cursor;
    float *inv, *pool;
    __nv_bfloat16 *hb, *ab, *wb;
    cudaGetSymbolAddress((void**)&cnt,    g_cnt);
    cudaGetSymbolAddress((void**)&offs,   g_offs);
    cudaGetSymbolAddress((void**)&cursor, g_cursor);
    cudaGetSymbolAddress((void**)&inv,    g_inv);
    cudaGetSymbolAddress((void**)&hb,     g_hb);
    cudaGetSymbolAddress((void**)&ab,     g_ab);
    cudaGetSymbolAddress((void**)&wb,     g_wb);
    cudaGetSymbolAddress((void**)&pool,   g_pool);

    const int smem = (DD + GR) * AS * (int)sizeof(__nv_bfloat16);
    cudaFuncSetAttribute(k_fat_gemm_count, cudaFuncAttributeMaxDynamicSharedMemorySize, smem);
    cudaFuncSetAttribute(k_gemm_bb, cudaFuncAttributeMaxDynamicSharedMemorySize, smem);

    const int gemm_grid   = (NN + GR - 1) / GR;
    const int count_grid  = (NE + GT - 1) / GT;
    const int wconv_grid  = (DD * DD / 4 + GT - 1) / GT;
    const int edge_grid   = (NN * 32 + 255) / 256;
    const int scat_blocks = (NE + 255) / 256;
    const int pad_blocks  = (NN + 255) / 256;

    // 0: fat = layer-1 GEMM + degree count + W2 convert
    k_fat_gemm_count<<<gemm_grid + count_grid + wconv_grid, GT, smem>>>(
        x, W1, hb, NN, dst, cnt, W2, wb, gemm_grid, count_grid);
    // 1: padded CSR offsets
    k_scan<<<1, SCAN_T>>>(cnt, offs, cursor, inv);
    // 2: scatter edges + grid-parallel pad fill
    k_scatter<<<scat_blocks + pad_blocks, 256>>>(src, dst, inv, cursor, offs, cnt, scat_blocks);
    // 3: layer-1 aggregation  <-- ncu captures this launch
    k_edge1<<<edge_grid, 256>>>(b1, ab);
    // 4: layer-2 GEMM (bf16 x bf16)
    k_gemm_bb<<<gemm_grid, GT, smem>>>(ab, wb, hb, NN);
    // 5: layer-2 aggregation + pool (also resets cnt)
    k_edge2_pool<<<edge_grid, 256>>>(b2, pool, cnt);
    // 6: classifier + log_softmax (also resets pool)
    k_finalize<<<1, 32>>>(pool, Wc, bc, out);
}